// round 14
// baseline (speedup 1.0000x reference)
#include <cuda_runtime.h>
#include <cuda_bf16.h>
#include <cuda_fp16.h>
#include <math.h>
#include <stdint.h>

#define MAXN 20000
#define MAXE 320000

// ---------------- device scratch (no allocs allowed) ----------------
__device__ int   g_is64;
__device__ int   g_src[MAXE];
__device__ int   g_dst[MAXE];
__device__ int   g_esrc[MAXE];
__device__ float g_ewn[MAXE];
__device__ float g_deg[MAXN];
__device__ float g_dinv[MAXN];
__device__ int   g_cnt[MAXN];
__device__ int   g_rowptr[MAXN + 1];
__device__ int   g_cursor[MAXN];
__device__ int   g_part[32];
__device__ int   g_off2[32];
__device__ int   g_total;
__device__ float g_base[(long long)MAXN * 512];   // permuted gate layout [r][P], P = hcol*4 + gate
__device__ float g_c[MAXN * 128];
__device__ __half g_hf[MAXN * 128];          // fp16 copy of h for the sequence props
// bf16-split activations (init path)
__device__ __nv_bfloat16 g_Ph[MAXN * 256];   // [P_h | P_c] hi
__device__ __nv_bfloat16 g_Pl[MAXN * 256];   // lo
// fp16-split activations (sequence path)
__device__ __half g_zh[MAXN * 128];
__device__ __half g_zl[MAXN * 128];
// bf16-split transposed weights (init/base), perm P = hcol*4 + gate
__device__ __nv_bfloat16 g_WTh[2 * 512 * 128];
__device__ __nv_bfloat16 g_WTl[2 * 512 * 128];
__device__ __nv_bfloat16 g_WIh[256 * 256];
__device__ __nv_bfloat16 g_WIl[256 * 256];
// fp16 single-precision weights for W_cell m=1 half (sequence path), permuted [P][k]
__device__ __half g_WF[512 * 128];

// ---------------- helpers ----------------
__device__ __forceinline__ float tanhA(float x) {
    float r; asm("tanh.approx.f32 %0, %1;" : "=f"(r) : "f"(x)); return r;
}
__device__ __forceinline__ float sigA(float x) {
    return fmaf(tanhA(0.5f * x), 0.5f, 0.5f);
}
__device__ __forceinline__ uint32_t smem_u32(const void* p) {
    uint32_t a;
    asm("{ .reg .u64 t; cvta.to.shared.u64 t, %1; cvt.u32.u64 %0, t; }" : "=r"(a) : "l"(p));
    return a;
}

#define CP16(dst, src, srcsz) \
    asm volatile("cp.async.ca.shared.global [%0], [%1], 16, %2;" \
        :: "r"(dst), "l"(src), "r"(srcsz))
#define CP_COMMIT() asm volatile("cp.async.commit_group;" ::: "memory")
#define CP_WAIT(nn) asm volatile("cp.async.wait_group %0;" :: "n"(nn) : "memory")

#define LDSM4(r0, r1, r2, r3, a) \
    asm volatile("ldmatrix.sync.aligned.m8n8.x4.shared.b16 {%0,%1,%2,%3}, [%4];" \
        : "=r"(r0), "=r"(r1), "=r"(r2), "=r"(r3) : "r"(a))

#define MMA16816(d, a0, a1, a2, a3, b0, b1) \
    asm volatile("mma.sync.aligned.m16n8k16.row.col.f32.bf16.bf16.f32 " \
        "{%0,%1,%2,%3}, {%4,%5,%6,%7}, {%8,%9}, {%0,%1,%2,%3};" \
        : "+f"((d)[0]), "+f"((d)[1]), "+f"((d)[2]), "+f"((d)[3]) \
        : "r"(a0), "r"(a1), "r"(a2), "r"(a3), "r"(b0), "r"(b1))

#define MMAH(d, a0, a1, a2, a3, b0, b1) \
    asm volatile("mma.sync.aligned.m16n8k16.row.col.f32.f16.f16.f32 " \
        "{%0,%1,%2,%3}, {%4,%5,%6,%7}, {%8,%9}, {%0,%1,%2,%3};" \
        : "+f"((d)[0]), "+f"((d)[1]), "+f"((d)[2]), "+f"((d)[3]) \
        : "r"(a0), "r"(a1), "r"(a2), "r"(a3), "r"(b0), "r"(b1))

// smem swizzle: 64B rows, 4x16B granules, conflict-free for 8-row LDSM phases
__device__ __forceinline__ uint32_t swz(int row, int g) {
    return (uint32_t)(row * 64 + ((g ^ ((row >> 1) & 3)) << 4));
}

// ---------------- setup kernels ----------------
__global__ void k_init(int n) {
    int i = blockIdx.x * blockDim.x + threadIdx.x;
    if (i < n) { g_deg[i] = 0.f; g_cnt[i] = 0; }
    if (i == 0) g_is64 = 1;
}

__global__ void k_detect(const unsigned int* __restrict__ w) {
    unsigned int v = w[2 * threadIdx.x + 1];
    if (v != 0u) g_is64 = 0;
}

__global__ void k_build(const void* __restrict__ ei, const float* __restrict__ ea, int E) {
    int e = blockIdx.x * blockDim.x + threadIdx.x;
    if (e >= E) return;
    int s, d;
    if (g_is64) {
        const long long* p = (const long long*)ei;
        s = (int)p[e]; d = (int)p[E + e];
    } else {
        const int* p = (const int*)ei;
        s = p[e]; d = p[E + e];
    }
    g_src[e] = s; g_dst[e] = d;
    atomicAdd(&g_deg[d], ea[e]);
    atomicAdd(&g_cnt[d], 1);
}

// hierarchical scan pass 1 (+ dinv fused)
__global__ void k_scan1(int n) {
    __shared__ int s[1024];
    int i = blockIdx.x * 1024 + threadIdx.x;
    if (i < n) g_dinv[i] = rsqrtf(g_deg[i] + 1.0f);
    int v = (i < n) ? g_cnt[i] : 0;
    s[threadIdx.x] = v;
    __syncthreads();
    for (int off = 1; off < 1024; off <<= 1) {
        int t = (threadIdx.x >= off) ? s[threadIdx.x - off] : 0;
        __syncthreads();
        s[threadIdx.x] += t;
        __syncthreads();
    }
    if (i < n) g_rowptr[i] = s[threadIdx.x] - v;   // local exclusive
    if (threadIdx.x == 1023) g_part[blockIdx.x] = s[1023];
}

__global__ void k_scan2(int nb) {
    int tid = threadIdx.x;                 // 32 threads
    int v = (tid < nb) ? g_part[tid] : 0;
    int incl = v;
    for (int o = 1; o < 32; o <<= 1) {
        int t = __shfl_up_sync(0xffffffffu, incl, o);
        if (tid >= o) incl += t;
    }
    if (tid < nb) g_off2[tid] = incl - v;
    if (tid == 31) g_total = incl;
}

__global__ void k_scan3(int n) {
    int i = blockIdx.x * 1024 + threadIdx.x;
    if (i < n) {
        int val = g_rowptr[i] + g_off2[blockIdx.x];
        g_rowptr[i] = val;
        g_cursor[i] = val;
    }
    if (i == 0) g_rowptr[n] = g_total;
}

__global__ void k_scatter(const float* __restrict__ ea, int E) {
    int e = blockIdx.x * blockDim.x + threadIdx.x;
    if (e >= E) return;
    int s = g_src[e], d = g_dst[e];
    int pos = atomicAdd(&g_cursor[d], 1);
    g_esrc[pos] = s;
    g_ewn[pos] = g_dinv[s] * ea[e] * g_dinv[d];
}

// fused weight transpose + permute + splits
// ids [0, 131072): W_cell bf16 split; perm P = hcol*4 + q <-> orig col q*128 + hcol
// ids [131072, 196608): W_init bf16 split, transposed [p][k]
// ids [196608, 262144): g_WF fp16 single of W_cell m=1 half, permuted [P][k]
__global__ void k_split(const float* __restrict__ Wc, const float* __restrict__ Wi) {
    int id = blockIdx.x * blockDim.x + threadIdx.x;   // 0 .. 262143
    if (id < 131072) {
        int m = id >> 16;
        int rem = id & 65535;
        int p = rem >> 7;
        int k = rem & 127;
        int hcol = p >> 2, q = p & 3;
        int nc = q * 128 + hcol;
        float v = Wc[(long long)(m * 128 + k) * 512 + nc];
        __nv_bfloat16 hb = __float2bfloat16_rn(v);
        float lf = v - __bfloat162float(hb);
        g_WTh[id] = hb;
        g_WTl[id] = __float2bfloat16_rn(lf);
    } else if (id < 196608) {
        int id2 = id - 131072;
        int p = id2 >> 8;
        int k = id2 & 255;
        float v = Wi[(long long)k * 256 + p];
        __nv_bfloat16 hb = __float2bfloat16_rn(v);
        float lf = v - __bfloat162float(hb);
        g_WIh[id2] = hb;
        g_WIl[id2] = __float2bfloat16_rn(lf);
    } else {
        int id3 = id - 196608;
        int P = id3 >> 7;
        int k = id3 & 127;
        int hcol = P >> 2, q = P & 3;
        float v = Wc[(long long)(128 + k) * 512 + q * 128 + hcol];
        g_WF[id3] = __float2half_rn(v);
    }
}

// ---------------- sparse propagate -> bf16 hi/lo split output (init path) ------
__global__ void k_prop(const float* __restrict__ x0, const float* __restrict__ x1,
                       __nv_bfloat16* __restrict__ oh, __nv_bfloat16* __restrict__ ol,
                       int ldo, int n) {
    const float* x = blockIdx.y ? x1 : x0;
    int coff = blockIdx.y * 128;
    int v = (blockIdx.x * blockDim.x + threadIdx.x) >> 5;
    int lane = threadIdx.x & 31;
    if (v >= n) return;
    int beg = g_rowptr[v], end = g_rowptr[v + 1];
    float ax = 0.f, ay = 0.f, az = 0.f, aw = 0.f;
    int e = beg;
    for (; e + 1 < end; e += 2) {
        int s0 = g_esrc[e], s1 = g_esrc[e + 1];
        float w0 = g_ewn[e], w1 = g_ewn[e + 1];
        float4 v0 = __ldg((const float4*)(x + (long long)s0 * 128) + lane);
        float4 v1 = __ldg((const float4*)(x + (long long)s1 * 128) + lane);
        ax = fmaf(w0, v0.x, ax); ay = fmaf(w0, v0.y, ay);
        az = fmaf(w0, v0.z, az); aw = fmaf(w0, v0.w, aw);
        ax = fmaf(w1, v1.x, ax); ay = fmaf(w1, v1.y, ay);
        az = fmaf(w1, v1.z, az); aw = fmaf(w1, v1.w, aw);
    }
    if (e < end) {
        int s0 = g_esrc[e];
        float w0 = g_ewn[e];
        float4 v0 = __ldg((const float4*)(x + (long long)s0 * 128) + lane);
        ax = fmaf(w0, v0.x, ax); ay = fmaf(w0, v0.y, ay);
        az = fmaf(w0, v0.z, az); aw = fmaf(w0, v0.w, aw);
    }
    float di = g_dinv[v];
    float w2 = di * di;
    float4 vv = __ldg((const float4*)(x + (long long)v * 128) + lane);
    ax = fmaf(w2, vv.x, ax); ay = fmaf(w2, vv.y, ay);
    az = fmaf(w2, vv.z, az); aw = fmaf(w2, vv.w, aw);
    float a[4] = {ax, ay, az, aw};
    unsigned short hs[4], ls[4];
#pragma unroll
    for (int m = 0; m < 4; m++) {
        __nv_bfloat16 hb = __float2bfloat16_rn(a[m]);
        float lf = a[m] - __bfloat162float(hb);
        __nv_bfloat16 lb = __float2bfloat16_rn(lf);
        hs[m] = *(unsigned short*)&hb;
        ls[m] = *(unsigned short*)&lb;
    }
    *(uint2*)(oh + (long long)v * ldo + coff + lane * 4) = *(uint2*)hs;
    *(uint2*)(ol + (long long)v * ldo + coff + lane * 4) = *(uint2*)ls;
}

// ---------------- sparse propagate from fp16 h -> fp16 hi/lo z (sequence) ----
__global__ void k_proph(int n) {
    int v = (blockIdx.x * blockDim.x + threadIdx.x) >> 5;
    int lane = threadIdx.x & 31;
    if (v >= n) return;
    int beg = g_rowptr[v], end = g_rowptr[v + 1];
    float ax = 0.f, ay = 0.f, az = 0.f, aw = 0.f;
    int e = beg;
    for (; e + 1 < end; e += 2) {
        int s0 = g_esrc[e], s1 = g_esrc[e + 1];
        float w0 = g_ewn[e], w1 = g_ewn[e + 1];
        uint2 h0 = __ldg((const uint2*)(g_hf + (long long)s0 * 128) + lane);
        uint2 h1 = __ldg((const uint2*)(g_hf + (long long)s1 * 128) + lane);
        float2 a0 = __half22float2(*(__half2*)&h0.x);
        float2 b0 = __half22float2(*(__half2*)&h0.y);
        float2 a1 = __half22float2(*(__half2*)&h1.x);
        float2 b1 = __half22float2(*(__half2*)&h1.y);
        ax = fmaf(w0, a0.x, ax); ay = fmaf(w0, a0.y, ay);
        az = fmaf(w0, b0.x, az); aw = fmaf(w0, b0.y, aw);
        ax = fmaf(w1, a1.x, ax); ay = fmaf(w1, a1.y, ay);
        az = fmaf(w1, b1.x, az); aw = fmaf(w1, b1.y, aw);
    }
    if (e < end) {
        int s0 = g_esrc[e];
        float w0 = g_ewn[e];
        uint2 h0 = __ldg((const uint2*)(g_hf + (long long)s0 * 128) + lane);
        float2 a0 = __half22float2(*(__half2*)&h0.x);
        float2 b0 = __half22float2(*(__half2*)&h0.y);
        ax = fmaf(w0, a0.x, ax); ay = fmaf(w0, a0.y, ay);
        az = fmaf(w0, b0.x, az); aw = fmaf(w0, b0.y, aw);
    }
    float di = g_dinv[v];
    float w2 = di * di;
    uint2 hv = __ldg((const uint2*)(g_hf + (long long)v * 128) + lane);
    float2 av = __half22float2(*(__half2*)&hv.x);
    float2 bv = __half22float2(*(__half2*)&hv.y);
    ax = fmaf(w2, av.x, ax); ay = fmaf(w2, av.y, ay);
    az = fmaf(w2, bv.x, az); aw = fmaf(w2, bv.y, aw);
    float a[4] = {ax, ay, az, aw};
    unsigned short hs[4], ls[4];
#pragma unroll
    for (int m = 0; m < 4; m++) {
        __half hb = __float2half_rn(a[m]);
        float lf = a[m] - __half2float(hb);
        __half lb = __float2half_rn(lf);
        hs[m] = *(unsigned short*)&hb;
        ls[m] = *(unsigned short*)&lb;
    }
    *(uint2*)(g_zh + (long long)v * 128 + lane * 4) = *(uint2*)hs;
    *(uint2*)(g_zl + (long long)v * 128 + lane * 4) = *(uint2*)ls;
}

// ---------------- sequence GEMM: fp16 2-term, M64 x N128 tile ----------------
// D = (Xh + Xl) @ W^T ; X fp16 hi/lo (22-bit activation), W single fp16.
// smem per 16KB stage: Ah[0,4K) Al[4K,8K) W[8K,16K); 64B swizzled rows; 2 stages.
// gates = D + base_perm; LSTM update g_c; write oseq (fp32) + g_hf (fp16).
__global__ void __launch_bounds__(256, 3)
k_mmaS(const float* __restrict__ baseb, float* __restrict__ oseq, int n) {
    extern __shared__ char sm[];
    const uint32_t sb = smem_u32(sm);
    const int tid = threadIdx.x;
    const int lane = tid & 31;
    const int wid = tid >> 5;
    const int m0 = blockIdx.x * 64;
    const int t = blockIdx.y;
    const int mw = (wid & 1) * 32;
    const int nw = (wid >> 1) * 32;

    float acc[2][4][4];
#pragma unroll
    for (int i = 0; i < 2; i++)
#pragma unroll
        for (int j = 0; j < 4; j++)
#pragma unroll
            for (int q = 0; q < 4; q++) acc[i][j][q] = 0.f;

    auto stage = [&](int ks) {
        uint32_t bufo = (uint32_t)(ks & 1) * 16384;
#pragma unroll
        for (int it = 0; it < 4; it++) {
            int id = tid + it * 256;        // 0..1023
            if (id < 512) {
                int arr = id >> 8;          // 0:zh 1:zl
                int rem = id & 255;
                int row = rem >> 2, g = rem & 3;
                uint32_t dst = sb + bufo + arr * 4096 + swz(row, g);
                const __half* src = (arr == 0 ? g_zh : g_zl)
                    + (size_t)(m0 + row) * 128 + ks * 32 + g * 8;
                int ok = (m0 + row < n) ? 16 : 0;
                CP16(dst, src, ok);
            } else {
                int rem = id - 512;         // 0..511
                int row = rem >> 2, g = rem & 3;
                uint32_t dst = sb + bufo + 8192 + swz(row, g);
                const __half* src = g_WF
                    + (size_t)(t * 128 + row) * 128 + ks * 32 + g * 8;
                CP16(dst, src, 16);
            }
        }
        CP_COMMIT();
    };

    stage(0);
#pragma unroll
    for (int ks = 0; ks < 4; ks++) {
        if (ks + 1 < 4) { stage(ks + 1); CP_WAIT(1); } else { CP_WAIT(0); }
        __syncthreads();
        uint32_t abase = sb + (uint32_t)(ks & 1) * 16384;
        uint32_t bbase = abase + 8192;
#pragma unroll
        for (int kc = 0; kc < 2; kc++) {
            uint32_t ah[2][4], al[2][4];
#pragma unroll
            for (int mf = 0; mf < 2; mf++) {
                int row = mw + mf * 16 + (lane & 15);
                int g = kc * 2 + (lane >> 4);
                uint32_t a = abase + swz(row, g);
                LDSM4(ah[mf][0], ah[mf][1], ah[mf][2], ah[mf][3], a);
                LDSM4(al[mf][0], al[mf][1], al[mf][2], al[mf][3], a + 4096);
            }
            uint32_t wf[2][4];
#pragma unroll
            for (int bp = 0; bp < 2; bp++) {
                int p = nw + bp * 16 + ((lane >> 4) << 3) + (lane & 7);
                int g = kc * 2 + ((lane >> 3) & 1);
                uint32_t a = bbase + swz(p, g);
                LDSM4(wf[bp][0], wf[bp][1], wf[bp][2], wf[bp][3], a);
            }
            // 16 MMAs: Xh term then Xl term (reuse distance 8)
#pragma unroll
            for (int bp = 0; bp < 2; bp++) {
                MMAH(acc[0][2 * bp],     ah[0][0], ah[0][1], ah[0][2], ah[0][3], wf[bp][0], wf[bp][1]);
                MMAH(acc[1][2 * bp],     ah[1][0], ah[1][1], ah[1][2], ah[1][3], wf[bp][0], wf[bp][1]);
                MMAH(acc[0][2 * bp + 1], ah[0][0], ah[0][1], ah[0][2], ah[0][3], wf[bp][2], wf[bp][3]);
                MMAH(acc[1][2 * bp + 1], ah[1][0], ah[1][1], ah[1][2], ah[1][3], wf[bp][2], wf[bp][3]);
            }
#pragma unroll
            for (int bp = 0; bp < 2; bp++) {
                MMAH(acc[0][2 * bp],     al[0][0], al[0][1], al[0][2], al[0][3], wf[bp][0], wf[bp][1]);
                MMAH(acc[1][2 * bp],     al[1][0], al[1][1], al[1][2], al[1][3], wf[bp][0], wf[bp][1]);
                MMAH(acc[0][2 * bp + 1], al[0][0], al[0][1], al[0][2], al[0][3], wf[bp][2], wf[bp][3]);
                MMAH(acc[1][2 * bp + 1], al[1][0], al[1][1], al[1][2], al[1][3], wf[bp][2], wf[bp][3]);
            }
        }
        __syncthreads();
    }

    // ---- LSTM epilogue ----
#pragma unroll
    for (int mf = 0; mf < 2; mf++) {
        int r0 = m0 + mw + mf * 16 + (lane >> 2);
        int r1 = r0 + 8;
#pragma unroll
        for (int nf = 0; nf < 4; nf++) {
            float d0 = acc[mf][nf][0], d1 = acc[mf][nf][1];
            float d2 = acc[mf][nf][2], d3 = acc[mf][nf][3];
            int c0 = nw + nf * 8 + (lane & 3) * 2;
            int P0 = t * 128 + c0;
            float2 b0 = make_float2(0.f, 0.f), b1 = make_float2(0.f, 0.f);
            if (r0 < n) b0 = *(const float2*)(baseb + (size_t)r0 * 512 + P0);
            if (r1 < n) b1 = *(const float2*)(baseb + (size_t)r1 * 512 + P0);
            float v0 = d0 + b0.x, v1 = d1 + b0.y;
            float v2 = d2 + b1.x, v3 = d3 + b1.y;
            float u0 = __shfl_xor_sync(0xffffffffu, v0, 1);
            float u1 = __shfl_xor_sync(0xffffffffu, v1, 1);
            float u2 = __shfl_xor_sync(0xffffffffu, v2, 1);
            float u3 = __shfl_xor_sync(0xffffffffu, v3, 1);
            if (!(lane & 1)) {
                // this lane: (i, f); partner: (o, g)
                int hcol = P0 >> 2;
                if (r0 < n) {
                    size_t ix = (size_t)r0 * 128 + hcol;
                    float cold = g_c[ix];
                    float cn = sigA(v1) * cold + sigA(v0) * tanhA(u1);
                    float hn = sigA(u0) * tanhA(cn);
                    g_c[ix] = cn; oseq[ix] = hn;
                    g_hf[ix] = __float2half_rn(hn);
                }
                if (r1 < n) {
                    size_t ix = (size_t)r1 * 128 + hcol;
                    float cold = g_c[ix];
                    float cn = sigA(v3) * cold + sigA(v2) * tanhA(u3);
                    float hn = sigA(u2) * tanhA(cn);
                    g_c[ix] = cn; oseq[ix] = hn;
                    g_hf[ix] = __float2half_rn(hn);
                }
            }
        }
    }
}

// ---------------- bf16 split-3 tensor GEMM (init + base precompute) ----------------
// mode 0: o512[r*512 + P] = D + bc[orig col]   (permuted base precompute)
// mode 2: init: elu(D + bi[col]) -> g_hf fp16 (cols<128) / g_c fp32
__global__ void __launch_bounds__(256, 2)
k_mma(const __nv_bfloat16* __restrict__ Ah, const __nv_bfloat16* __restrict__ Al, int lda,
      const __nv_bfloat16* __restrict__ Bh, const __nv_bfloat16* __restrict__ Bl,
      int K, const float* __restrict__ aux, float* __restrict__ o512, int n, int mode) {
    extern __shared__ char sm[];
    const uint32_t sb = smem_u32(sm);
    const int tid = threadIdx.x;
    const int lane = tid & 31;
    const int wid = tid >> 5;
    const int m0 = blockIdx.x * 128;
    const int t = blockIdx.y;
    const int mw = (wid & 3) * 32;
    const int nw = (wid >> 2) * 64;

    float acc[2][8][4];
#pragma unroll
    for (int i = 0; i < 2; i++)
#pragma unroll
        for (int j = 0; j < 8; j++)
#pragma unroll
            for (int q = 0; q < 4; q++) acc[i][j][q] = 0.f;

    const int nslab = K >> 5;

    auto stage = [&](int ks) {
        uint32_t bufo = (uint32_t)(ks % 3) * 32768;
#pragma unroll
        for (int it = 0; it < 8; it++) {
            int id = tid + it * 256;
            int arr = id >> 9;
            int rem = id & 511;
            int row = rem >> 2, g = rem & 3;
            uint32_t dst = sb + bufo + arr * 8192 + swz(row, g);
            if (arr < 2) {
                const __nv_bfloat16* src = (arr == 0 ? Ah : Al)
                    + (size_t)(m0 + row) * lda + ks * 32 + g * 8;
                int ok = (m0 + row < n) ? 16 : 0;
                CP16(dst, src, ok);
            } else {
                const __nv_bfloat16* src = (arr == 2 ? Bh : Bl)
                    + (size_t)(t * 128 + row) * K + ks * 32 + g * 8;
                CP16(dst, src, 16);
            }
        }
        CP_COMMIT();
    };

    stage(0);
    stage(1);
    for (int ks = 0; ks < nslab; ks++) {
        if (ks == nslab - 1) { CP_WAIT(0); } else { CP_WAIT(1); }
        __syncthreads();
        if (ks + 2 < nslab) stage(ks + 2);
        uint32_t abase = sb + (uint32_t)(ks % 3) * 32768;
        uint32_t bbase = abase + 16384;
#pragma unroll
        for (int kc = 0; kc < 2; kc++) {
            uint32_t ah[2][4], al[2][4];
#pragma unroll
            for (int mf = 0; mf < 2; mf++) {
                int row = mw + mf * 16 + (lane & 15);
                int g = kc * 2 + (lane >> 4);
                uint32_t a = abase + swz(row, g);
                LDSM4(ah[mf][0], ah[mf][1], ah[mf][2], ah[mf][3], a);
                LDSM4(al[mf][0], al[mf][1], al[mf][2], al[mf][3], a + 8192);
            }
#pragma unroll
            for (int bp = 0; bp < 4; bp++) {
                int p = nw + bp * 16 + ((lane >> 4) << 3) + (lane & 7);
                int g = kc * 2 + ((lane >> 3) & 1);
                uint32_t a = bbase + swz(p, g);
                uint32_t h0, h1, h2, h3, l0, l1, l2, l3;
                LDSM4(h0, h1, h2, h3, a);
                LDSM4(l0, l1, l2, l3, a + 8192);
                MMA16816(acc[0][2 * bp],     ah[0][0], ah[0][1], ah[0][2], ah[0][3], h0, h1);
                MMA16816(acc[1][2 * bp],     ah[1][0], ah[1][1], ah[1][2], ah[1][3], h0, h1);
                MMA16816(acc[0][2 * bp + 1], ah[0][0], ah[0][1], ah[0][2], ah[0][3], h2, h3);
                MMA16816(acc[1][2 * bp + 1], ah[1][0], ah[1][1], ah[1][2], ah[1][3], h2, h3);
                MMA16816(acc[0][2 * bp],     ah[0][0], ah[0][1], ah[0][2], ah[0][3], l0, l1);
                MMA16816(acc[1][2 * bp],     ah[1][0], ah[1][1], ah[1][2], ah[1][3], l0, l1);
                MMA16816(acc[0][2 * bp + 1], ah[0][0], ah[0][1], ah[0][2], ah[0][3], l2, l3);
                MMA16816(acc[1][2 * bp + 1], ah[1][0], ah[1][1], ah[1][2], ah[1][3], l2, l3);
                MMA16816(acc[0][2 * bp],     al[0][0], al[0][1], al[0][2], al[0][3], h0, h1);
                MMA16816(acc[1][2 * bp],     al[1][0], al[1][1], al[1][2], al[1][3], h0, h1);
                MMA16816(acc[0][2 * bp + 1], al[0][0], al[0][1], al[0][2], al[0][3], h2, h3);
                MMA16816(acc[1][2 * bp + 1], al[1][0], al[1][1], al[1][2], al[1][3], h2, h3);
            }
        }
    }

#pragma unroll
    for (int mf = 0; mf < 2; mf++) {
        int r0 = m0 + mw + mf * 16 + (lane >> 2);
        int r1 = r0 + 8;
#pragma unroll
        for (int nf = 0; nf < 8; nf++) {
            float d0 = acc[mf][nf][0], d1 = acc[mf][nf][1];
            float d2 = acc[mf][nf][2], d3 = acc[mf][nf][3];
            int c0 = nw + nf * 8 + (lane & 3) * 2;
            if (mode == 2) {
                int gc = t * 128 + c0;
                float2 bb = *(const float2*)(aux + gc);
                if (r0 < n) {
                    float e0 = d0 + bb.x, e1 = d1 + bb.y;
                    e0 = (e0 > 0.f) ? e0 : expm1f(e0);
                    e1 = (e1 > 0.f) ? e1 : expm1f(e1);
                    if (gc < 128) {
                        __half2 o = __floats2half2_rn(e0, e1);
                        *(__half2*)(g_hf + (size_t)r0 * 128 + gc) = o;
                    } else {
                        float2 o; o.x = e0; o.y = e1;
                        *(float2*)(g_c + (size_t)r0 * 128 + (gc - 128)) = o;
                    }
                }
                if (r1 < n) {
                    float e0 = d2 + bb.x, e1 = d3 + bb.y;
                    e0 = (e0 > 0.f) ? e0 : expm1f(e0);
                    e1 = (e1 > 0.f) ? e1 : expm1f(e1);
                    if (gc < 128) {
                        __half2 o = __floats2half2_rn(e0, e1);
                        *(__half2*)(g_hf + (size_t)r1 * 128 + gc) = o;
                    } else {
                        float2 o; o.x = e0; o.y = e1;
                        *(float2*)(g_c + (size_t)r1 * 128 + (gc - 128)) = o;
                    }
                }
            } else {
                int P = t * 128 + c0;
                float bb0 = aux[(P & 3) * 128 + (P >> 2)];
                float bb1 = aux[((P + 1) & 3) * 128 + ((P + 1) >> 2)];
                if (r0 < n) {
                    float2 o; o.x = d0 + bb0; o.y = d1 + bb1;
                    *(float2*)(o512 + (size_t)r0 * 512 + P) = o;
                }
                if (r1 < n) {
                    float2 o; o.x = d2 + bb0; o.y = d3 + bb1;
                    *(float2*)(o512 + (size_t)r1 * 512 + P) = o;
                }
            }
        }
    }
}

// ---------------- host launcher ----------------
extern "C" void kernel_launch(void* const* d_in, const int* in_sizes, int n_in,
                              void* d_out, int out_size) {
    const float* h  = (const float*)d_in[0];
    const float* c  = (const float*)d_in[1];
    const void*  ei = d_in[2];
    const float* ea = (const float*)d_in[3];
    const float* Wi = (const float*)d_in[4];
    const float* bi = (const float*)d_in[5];
    const float* Wc = (const float*)d_in[6];
    const float* bc = (const float*)d_in[7];
    float* out = (float*)d_out;

    int n   = in_sizes[0] / 128;
    int E   = in_sizes[3];
    int seq = out_size / (n * 128);

    static float* p_base = nullptr;
    static __nv_bfloat16 *p_Ph, *p_Pl, *p_WTh, *p_WTl, *p_WIh, *p_WIl;
    if (!p_base) {
        cudaGetSymbolAddress((void**)&p_base, g_base);
        cudaGetSymbolAddress((void**)&p_Ph, g_Ph);
        cudaGetSymbolAddress((void**)&p_Pl, g_Pl);
        cudaGetSymbolAddress((void**)&p_WTh, g_WTh);
        cudaGetSymbolAddress((void**)&p_WTl, g_WTl);
        cudaGetSymbolAddress((void**)&p_WIh, g_WIh);
        cudaGetSymbolAddress((void**)&p_WIl, g_WIl);
        cudaFuncSetAttribute(k_mma, cudaFuncAttributeMaxDynamicSharedMemorySize, 98304);
        cudaFuncSetAttribute(k_mmaS, cudaFuncAttributeMaxDynamicSharedMemorySize, 32768);
    }

    int nb256 = (n + 255) / 256;
    int eb256 = (E + 255) / 256;
    int nb1024 = (n + 1023) / 1024;
    int mtiles = (n + 127) / 128;
    int mt64 = (n + 63) / 64;
    int prop_blocks = (n * 32 + 255) / 256;
    size_t smem_sz = 98304;
    size_t smemS = 32768;

    // ---- graph setup (per launch; deterministic) ----
    k_init<<<nb256, 256>>>(n);
    k_detect<<<1, 128>>>((const unsigned int*)ei);
    k_build<<<eb256, 256>>>(ei, ea, E);
    k_scan1<<<nb1024, 1024>>>(n);        // also computes dinv
    k_scan2<<<1, 32>>>(nb1024);
    k_scan3<<<nb1024, 1024>>>(n);
    k_scatter<<<eb256, 256>>>(ea, E);
    k_split<<<1024, 256>>>(Wc, Wi);

    // ---- loop-invariant precompute ----
    k_prop<<<dim3(prop_blocks, 2), 256>>>(h, c, p_Ph, p_Pl, 256, n);
    // init: elu(Phc @ W_init + b_init) -> g_hf (fp16), g_c
    k_mma<<<dim3(mtiles, 2), 256, smem_sz>>>(p_Ph, p_Pl, 256, p_WIh, p_WIl, 256,
                                             bi, nullptr, n, 2);
    // base_perm = P_h @ Wc[0:128] + b_cell
    k_mma<<<dim3(mtiles, 4), 256, smem_sz>>>(p_Ph, p_Pl, 256, p_WTh, p_WTl, 128,
                                             bc, p_base, n, 0);

    // ---- sequence: prop reads fp16 h (g_hf), GEMM writes out + g_hf ----
    for (int tt = 0; tt < seq; tt++) {
        k_proph<<<prop_blocks, 256>>>(n);
        float* odst = out + (long long)tt * n * 128;
        k_mmaS<<<dim3(mt64, 4), 256, smemS>>>(p_base, odst, n);
    }
}

// round 15
// speedup vs baseline: 1.0679x; 1.0679x over previous
#include <cuda_runtime.h>
#include <cuda_bf16.h>
#include <cuda_fp16.h>
#include <math.h>
#include <stdint.h>

#define MAXN 20000
#define MAXE 320000

// ---------------- device scratch (no allocs allowed) ----------------
__device__ int   g_is64;
__device__ int   g_src[MAXE];
__device__ int   g_dst[MAXE];
__device__ int   g_esrc[MAXE];
__device__ float g_ewn[MAXE];
__device__ float g_deg[MAXN];
__device__ float g_dinv[MAXN];
__device__ int   g_cnt[MAXN];
__device__ int   g_rowptr[MAXN + 1];
__device__ int   g_cursor[MAXN];
__device__ int   g_part[32];
__device__ int   g_off2[32];
__device__ int   g_total;
__device__ float g_base[(long long)MAXN * 512];   // permuted gate layout [r][P], P = hcol*4 + gate
__device__ float g_h[MAXN * 128];
__device__ float g_c[MAXN * 128];
// bf16-split activations (init path)
__device__ __nv_bfloat16 g_Ph[MAXN * 256];   // [P_h | P_c] hi
__device__ __nv_bfloat16 g_Pl[MAXN * 256];   // lo
// fp16-split activations (sequence path)
__device__ __half g_zh[MAXN * 128];
__device__ __half g_zl[MAXN * 128];
// bf16-split transposed weights (init/base), perm P = hcol*4 + gate
__device__ __nv_bfloat16 g_WTh[2 * 512 * 128];
__device__ __nv_bfloat16 g_WTl[2 * 512 * 128];
__device__ __nv_bfloat16 g_WIh[256 * 256];
__device__ __nv_bfloat16 g_WIl[256 * 256];
// fp16 single-precision weights for W_cell m=1 half (sequence path), permuted [P][k]
__device__ __half g_WF[512 * 128];

// ---------------- helpers ----------------
__device__ __forceinline__ float tanhA(float x) {
    float r; asm("tanh.approx.f32 %0, %1;" : "=f"(r) : "f"(x)); return r;
}
__device__ __forceinline__ float sigA(float x) {
    return fmaf(tanhA(0.5f * x), 0.5f, 0.5f);
}
__device__ __forceinline__ uint32_t smem_u32(const void* p) {
    uint32_t a;
    asm("{ .reg .u64 t; cvta.to.shared.u64 t, %1; cvt.u32.u64 %0, t; }" : "=r"(a) : "l"(p));
    return a;
}

#define CP16(dst, src, srcsz) \
    asm volatile("cp.async.ca.shared.global [%0], [%1], 16, %2;" \
        :: "r"(dst), "l"(src), "r"(srcsz))
#define CP_COMMIT() asm volatile("cp.async.commit_group;" ::: "memory")
#define CP_WAIT(nn) asm volatile("cp.async.wait_group %0;" :: "n"(nn) : "memory")

#define LDSM4(r0, r1, r2, r3, a) \
    asm volatile("ldmatrix.sync.aligned.m8n8.x4.shared.b16 {%0,%1,%2,%3}, [%4];" \
        : "=r"(r0), "=r"(r1), "=r"(r2), "=r"(r3) : "r"(a))

#define MMA16816(d, a0, a1, a2, a3, b0, b1) \
    asm volatile("mma.sync.aligned.m16n8k16.row.col.f32.bf16.bf16.f32 " \
        "{%0,%1,%2,%3}, {%4,%5,%6,%7}, {%8,%9}, {%0,%1,%2,%3};" \
        : "+f"((d)[0]), "+f"((d)[1]), "+f"((d)[2]), "+f"((d)[3]) \
        : "r"(a0), "r"(a1), "r"(a2), "r"(a3), "r"(b0), "r"(b1))

#define MMAH(d, a0, a1, a2, a3, b0, b1) \
    asm volatile("mma.sync.aligned.m16n8k16.row.col.f32.f16.f16.f32 " \
        "{%0,%1,%2,%3}, {%4,%5,%6,%7}, {%8,%9}, {%0,%1,%2,%3};" \
        : "+f"((d)[0]), "+f"((d)[1]), "+f"((d)[2]), "+f"((d)[3]) \
        : "r"(a0), "r"(a1), "r"(a2), "r"(a3), "r"(b0), "r"(b1))

// smem swizzle: 64B rows, 4x16B granules, conflict-free for 8-row LDSM phases
__device__ __forceinline__ uint32_t swz(int row, int g) {
    return (uint32_t)(row * 64 + ((g ^ ((row >> 1) & 3)) << 4));
}

// ---------------- setup kernels ----------------
__global__ void k_init(int n) {
    int i = blockIdx.x * blockDim.x + threadIdx.x;
    if (i < n) { g_deg[i] = 0.f; g_cnt[i] = 0; }
    if (i == 0) g_is64 = 1;
}

__global__ void k_detect(const unsigned int* __restrict__ w) {
    unsigned int v = w[2 * threadIdx.x + 1];
    if (v != 0u) g_is64 = 0;
}

__global__ void k_build(const void* __restrict__ ei, const float* __restrict__ ea, int E) {
    int e = blockIdx.x * blockDim.x + threadIdx.x;
    if (e >= E) return;
    int s, d;
    if (g_is64) {
        const long long* p = (const long long*)ei;
        s = (int)p[e]; d = (int)p[E + e];
    } else {
        const int* p = (const int*)ei;
        s = p[e]; d = p[E + e];
    }
    g_src[e] = s; g_dst[e] = d;
    atomicAdd(&g_deg[d], ea[e]);
    atomicAdd(&g_cnt[d], 1);
}

// hierarchical scan pass 1 (+ dinv fused)
__global__ void k_scan1(int n) {
    __shared__ int s[1024];
    int i = blockIdx.x * 1024 + threadIdx.x;
    if (i < n) g_dinv[i] = rsqrtf(g_deg[i] + 1.0f);
    int v = (i < n) ? g_cnt[i] : 0;
    s[threadIdx.x] = v;
    __syncthreads();
    for (int off = 1; off < 1024; off <<= 1) {
        int t = (threadIdx.x >= off) ? s[threadIdx.x - off] : 0;
        __syncthreads();
        s[threadIdx.x] += t;
        __syncthreads();
    }
    if (i < n) g_rowptr[i] = s[threadIdx.x] - v;   // local exclusive
    if (threadIdx.x == 1023) g_part[blockIdx.x] = s[1023];
}

__global__ void k_scan2(int nb) {
    int tid = threadIdx.x;                 // 32 threads
    int v = (tid < nb) ? g_part[tid] : 0;
    int incl = v;
    for (int o = 1; o < 32; o <<= 1) {
        int t = __shfl_up_sync(0xffffffffu, incl, o);
        if (tid >= o) incl += t;
    }
    if (tid < nb) g_off2[tid] = incl - v;
    if (tid == 31) g_total = incl;
}

__global__ void k_scan3(int n) {
    int i = blockIdx.x * 1024 + threadIdx.x;
    if (i < n) {
        int val = g_rowptr[i] + g_off2[blockIdx.x];
        g_rowptr[i] = val;
        g_cursor[i] = val;
    }
    if (i == 0) g_rowptr[n] = g_total;
}

__global__ void k_scatter(const float* __restrict__ ea, int E) {
    int e = blockIdx.x * blockDim.x + threadIdx.x;
    if (e >= E) return;
    int s = g_src[e], d = g_dst[e];
    int pos = atomicAdd(&g_cursor[d], 1);
    g_esrc[pos] = s;
    g_ewn[pos] = g_dinv[s] * ea[e] * g_dinv[d];
}

// fused weight transpose + permute + splits
// ids [0, 131072): W_cell bf16 split; perm P = hcol*4 + q <-> orig col q*128 + hcol
// ids [131072, 196608): W_init bf16 split, transposed [p][k]
// ids [196608, 262144): g_WF fp16 single of W_cell m=1 half, permuted [P][k]
__global__ void k_split(const float* __restrict__ Wc, const float* __restrict__ Wi) {
    int id = blockIdx.x * blockDim.x + threadIdx.x;   // 0 .. 262143
    if (id < 131072) {
        int m = id >> 16;
        int rem = id & 65535;
        int p = rem >> 7;
        int k = rem & 127;
        int hcol = p >> 2, q = p & 3;
        int nc = q * 128 + hcol;
        float v = Wc[(long long)(m * 128 + k) * 512 + nc];
        __nv_bfloat16 hb = __float2bfloat16_rn(v);
        float lf = v - __bfloat162float(hb);
        g_WTh[id] = hb;
        g_WTl[id] = __float2bfloat16_rn(lf);
    } else if (id < 196608) {
        int id2 = id - 131072;
        int p = id2 >> 8;
        int k = id2 & 255;
        float v = Wi[(long long)k * 256 + p];
        __nv_bfloat16 hb = __float2bfloat16_rn(v);
        float lf = v - __bfloat162float(hb);
        g_WIh[id2] = hb;
        g_WIl[id2] = __float2bfloat16_rn(lf);
    } else {
        int id3 = id - 196608;
        int P = id3 >> 7;
        int k = id3 & 127;
        int hcol = P >> 2, q = P & 3;
        float v = Wc[(long long)(128 + k) * 512 + q * 128 + hcol];
        g_WF[id3] = __float2half_rn(v);
    }
}

// ---------------- sparse propagate -> bf16 hi/lo split output (init path) ------
__global__ void k_prop(const float* __restrict__ x0, const float* __restrict__ x1,
                       __nv_bfloat16* __restrict__ oh, __nv_bfloat16* __restrict__ ol,
                       int ldo, int n) {
    const float* x = blockIdx.y ? x1 : x0;
    int coff = blockIdx.y * 128;
    int v = (blockIdx.x * blockDim.x + threadIdx.x) >> 5;
    int lane = threadIdx.x & 31;
    if (v >= n) return;
    int beg = g_rowptr[v], end = g_rowptr[v + 1];
    float ax = 0.f, ay = 0.f, az = 0.f, aw = 0.f;
    int e = beg;
    for (; e + 1 < end; e += 2) {
        int s0 = g_esrc[e], s1 = g_esrc[e + 1];
        float w0 = g_ewn[e], w1 = g_ewn[e + 1];
        float4 v0 = __ldg((const float4*)(x + (long long)s0 * 128) + lane);
        float4 v1 = __ldg((const float4*)(x + (long long)s1 * 128) + lane);
        ax = fmaf(w0, v0.x, ax); ay = fmaf(w0, v0.y, ay);
        az = fmaf(w0, v0.z, az); aw = fmaf(w0, v0.w, aw);
        ax = fmaf(w1, v1.x, ax); ay = fmaf(w1, v1.y, ay);
        az = fmaf(w1, v1.z, az); aw = fmaf(w1, v1.w, aw);
    }
    if (e < end) {
        int s0 = g_esrc[e];
        float w0 = g_ewn[e];
        float4 v0 = __ldg((const float4*)(x + (long long)s0 * 128) + lane);
        ax = fmaf(w0, v0.x, ax); ay = fmaf(w0, v0.y, ay);
        az = fmaf(w0, v0.z, az); aw = fmaf(w0, v0.w, aw);
    }
    float di = g_dinv[v];
    float w2 = di * di;
    float4 vv = __ldg((const float4*)(x + (long long)v * 128) + lane);
    ax = fmaf(w2, vv.x, ax); ay = fmaf(w2, vv.y, ay);
    az = fmaf(w2, vv.z, az); aw = fmaf(w2, vv.w, aw);
    float a[4] = {ax, ay, az, aw};
    unsigned short hs[4], ls[4];
#pragma unroll
    for (int m = 0; m < 4; m++) {
        __nv_bfloat16 hb = __float2bfloat16_rn(a[m]);
        float lf = a[m] - __bfloat162float(hb);
        __nv_bfloat16 lb = __float2bfloat16_rn(lf);
        hs[m] = *(unsigned short*)&hb;
        ls[m] = *(unsigned short*)&lb;
    }
    *(uint2*)(oh + (long long)v * ldo + coff + lane * 4) = *(uint2*)hs;
    *(uint2*)(ol + (long long)v * ldo + coff + lane * 4) = *(uint2*)ls;
}

// ---------------- sparse propagate -> fp16 hi/lo split output (sequence path) ----
// edge loop unrolled x4 for MLP
__global__ void k_prop16(const float* __restrict__ x, int n) {
    int v = (blockIdx.x * blockDim.x + threadIdx.x) >> 5;
    int lane = threadIdx.x & 31;
    if (v >= n) return;
    int beg = g_rowptr[v], end = g_rowptr[v + 1];
    float ax = 0.f, ay = 0.f, az = 0.f, aw = 0.f;
    int e = beg;
    for (; e + 3 < end; e += 4) {
        int s0 = g_esrc[e], s1 = g_esrc[e + 1];
        int s2 = g_esrc[e + 2], s3 = g_esrc[e + 3];
        float w0 = g_ewn[e], w1 = g_ewn[e + 1];
        float w2 = g_ewn[e + 2], w3 = g_ewn[e + 3];
        float4 v0 = __ldg((const float4*)(x + (long long)s0 * 128) + lane);
        float4 v1 = __ldg((const float4*)(x + (long long)s1 * 128) + lane);
        float4 v2 = __ldg((const float4*)(x + (long long)s2 * 128) + lane);
        float4 v3 = __ldg((const float4*)(x + (long long)s3 * 128) + lane);
        ax = fmaf(w0, v0.x, ax); ay = fmaf(w0, v0.y, ay);
        az = fmaf(w0, v0.z, az); aw = fmaf(w0, v0.w, aw);
        ax = fmaf(w1, v1.x, ax); ay = fmaf(w1, v1.y, ay);
        az = fmaf(w1, v1.z, az); aw = fmaf(w1, v1.w, aw);
        ax = fmaf(w2, v2.x, ax); ay = fmaf(w2, v2.y, ay);
        az = fmaf(w2, v2.z, az); aw = fmaf(w2, v2.w, aw);
        ax = fmaf(w3, v3.x, ax); ay = fmaf(w3, v3.y, ay);
        az = fmaf(w3, v3.z, az); aw = fmaf(w3, v3.w, aw);
    }
    for (; e < end; e++) {
        int s0 = g_esrc[e];
        float w0 = g_ewn[e];
        float4 v0 = __ldg((const float4*)(x + (long long)s0 * 128) + lane);
        ax = fmaf(w0, v0.x, ax); ay = fmaf(w0, v0.y, ay);
        az = fmaf(w0, v0.z, az); aw = fmaf(w0, v0.w, aw);
    }
    float di = g_dinv[v];
    float w2 = di * di;
    float4 vv = __ldg((const float4*)(x + (long long)v * 128) + lane);
    ax = fmaf(w2, vv.x, ax); ay = fmaf(w2, vv.y, ay);
    az = fmaf(w2, vv.z, az); aw = fmaf(w2, vv.w, aw);
    float a[4] = {ax, ay, az, aw};
    unsigned short hs[4], ls[4];
#pragma unroll
    for (int m = 0; m < 4; m++) {
        __half hb = __float2half_rn(a[m]);
        float lf = a[m] - __half2float(hb);
        __half lb = __float2half_rn(lf);
        hs[m] = *(unsigned short*)&hb;
        ls[m] = *(unsigned short*)&lb;
    }
    *(uint2*)(g_zh + (long long)v * 128 + lane * 4) = *(uint2*)hs;
    *(uint2*)(g_zl + (long long)v * 128 + lane * 4) = *(uint2*)ls;
}

// ---------------- sequence GEMM: fp16 2-term, M64 x N128 tile, 3-stage ring ----
// D = (Xh + Xl) @ W^T ; X fp16 hi/lo (22-bit activation), W single fp16.
// smem per 16KB stage: Ah[0,4K) Al[4K,8K) W[8K,16K); 64B swizzled rows; 3 stages.
// gates = D + base_perm; LSTM update g_c; write oseq.
__global__ void __launch_bounds__(256, 3)
k_mmaS(const float* __restrict__ baseb, float* __restrict__ oseq, int n) {
    extern __shared__ char sm[];
    const uint32_t sb = smem_u32(sm);
    const int tid = threadIdx.x;
    const int lane = tid & 31;
    const int wid = tid >> 5;
    const int m0 = blockIdx.x * 64;
    const int t = blockIdx.y;
    const int mw = (wid & 1) * 32;
    const int nw = (wid >> 1) * 32;

    float acc[2][4][4];
#pragma unroll
    for (int i = 0; i < 2; i++)
#pragma unroll
        for (int j = 0; j < 4; j++)
#pragma unroll
            for (int q = 0; q < 4; q++) acc[i][j][q] = 0.f;

    auto stage = [&](int ks) {
        uint32_t bufo = (uint32_t)(ks % 3) * 16384;
#pragma unroll
        for (int it = 0; it < 4; it++) {
            int id = tid + it * 256;        // 0..1023
            if (id < 512) {
                int arr = id >> 8;          // 0:zh 1:zl
                int rem = id & 255;
                int row = rem >> 2, g = rem & 3;
                uint32_t dst = sb + bufo + arr * 4096 + swz(row, g);
                const __half* src = (arr == 0 ? g_zh : g_zl)
                    + (size_t)(m0 + row) * 128 + ks * 32 + g * 8;
                int ok = (m0 + row < n) ? 16 : 0;
                CP16(dst, src, ok);
            } else {
                int rem = id - 512;         // 0..511
                int row = rem >> 2, g = rem & 3;
                uint32_t dst = sb + bufo + 8192 + swz(row, g);
                const __half* src = g_WF
                    + (size_t)(t * 128 + row) * 128 + ks * 32 + g * 8;
                CP16(dst, src, 16);
            }
        }
        CP_COMMIT();
    };

    stage(0);
    stage(1);
#pragma unroll
    for (int ks = 0; ks < 4; ks++) {
        if (ks == 3) { CP_WAIT(0); } else { CP_WAIT(1); }
        __syncthreads();
        if (ks + 2 < 4) stage(ks + 2);
        uint32_t abase = sb + (uint32_t)(ks % 3) * 16384;
        uint32_t bbase = abase + 8192;
#pragma unroll
        for (int kc = 0; kc < 2; kc++) {
            uint32_t ah[2][4], al[2][4];
#pragma unroll
            for (int mf = 0; mf < 2; mf++) {
                int row = mw + mf * 16 + (lane & 15);
                int g = kc * 2 + (lane >> 4);
                uint32_t a = abase + swz(row, g);
                LDSM4(ah[mf][0], ah[mf][1], ah[mf][2], ah[mf][3], a);
                LDSM4(al[mf][0], al[mf][1], al[mf][2], al[mf][3], a + 4096);
            }
            uint32_t wf[2][4];
#pragma unroll
            for (int bp = 0; bp < 2; bp++) {
                int p = nw + bp * 16 + ((lane >> 4) << 3) + (lane & 7);
                int g = kc * 2 + ((lane >> 3) & 1);
                uint32_t a = bbase + swz(p, g);
                LDSM4(wf[bp][0], wf[bp][1], wf[bp][2], wf[bp][3], a);
            }
            // 16 MMAs: Xh term then Xl term (reuse distance 8)
#pragma unroll
            for (int bp = 0; bp < 2; bp++) {
                MMAH(acc[0][2 * bp],     ah[0][0], ah[0][1], ah[0][2], ah[0][3], wf[bp][0], wf[bp][1]);
                MMAH(acc[1][2 * bp],     ah[1][0], ah[1][1], ah[1][2], ah[1][3], wf[bp][0], wf[bp][1]);
                MMAH(acc[0][2 * bp + 1], ah[0][0], ah[0][1], ah[0][2], ah[0][3], wf[bp][2], wf[bp][3]);
                MMAH(acc[1][2 * bp + 1], ah[1][0], ah[1][1], ah[1][2], ah[1][3], wf[bp][2], wf[bp][3]);
            }
#pragma unroll
            for (int bp = 0; bp < 2; bp++) {
                MMAH(acc[0][2 * bp],     al[0][0], al[0][1], al[0][2], al[0][3], wf[bp][0], wf[bp][1]);
                MMAH(acc[1][2 * bp],     al[1][0], al[1][1], al[1][2], al[1][3], wf[bp][0], wf[bp][1]);
                MMAH(acc[0][2 * bp + 1], al[0][0], al[0][1], al[0][2], al[0][3], wf[bp][2], wf[bp][3]);
                MMAH(acc[1][2 * bp + 1], al[1][0], al[1][1], al[1][2], al[1][3], wf[bp][2], wf[bp][3]);
            }
        }
        __syncthreads();
    }

    // ---- LSTM epilogue ----
#pragma unroll
    for (int mf = 0; mf < 2; mf++) {
        int r0 = m0 + mw + mf * 16 + (lane >> 2);
        int r1 = r0 + 8;
#pragma unroll
        for (int nf = 0; nf < 4; nf++) {
            float d0 = acc[mf][nf][0], d1 = acc[mf][nf][1];
            float d2 = acc[mf][nf][2], d3 = acc[mf][nf][3];
            int c0 = nw + nf * 8 + (lane & 3) * 2;
            int P0 = t * 128 + c0;
            float2 b0 = make_float2(0.f, 0.f), b1 = make_float2(0.f, 0.f);
            if (r0 < n) b0 = *(const float2*)(baseb + (size_t)r0 * 512 + P0);
            if (r1 < n) b1 = *(const float2*)(baseb + (size_t)r1 * 512 + P0);
            float v0 = d0 + b0.x, v1 = d1 + b0.y;
            float v2 = d2 + b1.x, v3 = d3 + b1.y;
            float u0 = __shfl_xor_sync(0xffffffffu, v0, 1);
            float u1 = __shfl_xor_sync(0xffffffffu, v1, 1);
            float u2 = __shfl_xor_sync(0xffffffffu, v2, 1);
            float u3 = __shfl_xor_sync(0xffffffffu, v3, 1);
            if (!(lane & 1)) {
                // this lane: (i, f); partner: (o, g)
                int hcol = P0 >> 2;
                if (r0 < n) {
                    size_t ix = (size_t)r0 * 128 + hcol;
                    float cold = g_c[ix];
                    float cn = sigA(v1) * cold + sigA(v0) * tanhA(u1);
                    float hn = sigA(u0) * tanhA(cn);
                    g_c[ix] = cn; oseq[ix] = hn;
                }
                if (r1 < n) {
                    size_t ix = (size_t)r1 * 128 + hcol;
                    float cold = g_c[ix];
                    float cn = sigA(v3) * cold + sigA(v2) * tanhA(u3);
                    float hn = sigA(u2) * tanhA(cn);
                    g_c[ix] = cn; oseq[ix] = hn;
                }
            }
        }
    }
}

// ---------------- bf16 split-3 tensor GEMM (init + base precompute) ----------------
// mode 0: o512[r*512 + P] = D + bc[orig col]   (permuted base precompute)
// mode 2: init: elu(D + bi[col]) -> g_h (cols<128) / g_c
__global__ void __launch_bounds__(256, 2)
k_mma(const __nv_bfloat16* __restrict__ Ah, const __nv_bfloat16* __restrict__ Al, int lda,
      const __nv_bfloat16* __restrict__ Bh, const __nv_bfloat16* __restrict__ Bl,
      int K, const float* __restrict__ aux, float* __restrict__ o512, int n, int mode) {
    extern __shared__ char sm[];
    const uint32_t sb = smem_u32(sm);
    const int tid = threadIdx.x;
    const int lane = tid & 31;
    const int wid = tid >> 5;
    const int m0 = blockIdx.x * 128;
    const int t = blockIdx.y;
    const int mw = (wid & 3) * 32;
    const int nw = (wid >> 2) * 64;

    float acc[2][8][4];
#pragma unroll
    for (int i = 0; i < 2; i++)
#pragma unroll
        for (int j = 0; j < 8; j++)
#pragma unroll
            for (int q = 0; q < 4; q++) acc[i][j][q] = 0.f;

    const int nslab = K >> 5;

    auto stage = [&](int ks) {
        uint32_t bufo = (uint32_t)(ks % 3) * 32768;
#pragma unroll
        for (int it = 0; it < 8; it++) {
            int id = tid + it * 256;
            int arr = id >> 9;
            int rem = id & 511;
            int row = rem >> 2, g = rem & 3;
            uint32_t dst = sb + bufo + arr * 8192 + swz(row, g);
            if (arr < 2) {
                const __nv_bfloat16* src = (arr == 0 ? Ah : Al)
                    + (size_t)(m0 + row) * lda + ks * 32 + g * 8;
                int ok = (m0 + row < n) ? 16 : 0;
                CP16(dst, src, ok);
            } else {
                const __nv_bfloat16* src = (arr == 2 ? Bh : Bl)
                    + (size_t)(t * 128 + row) * K + ks * 32 + g * 8;
                CP16(dst, src, 16);
            }
        }
        CP_COMMIT();
    };

    stage(0);
    stage(1);
    for (int ks = 0; ks < nslab; ks++) {
        if (ks == nslab - 1) { CP_WAIT(0); } else { CP_WAIT(1); }
        __syncthreads();
        if (ks + 2 < nslab) stage(ks + 2);
        uint32_t abase = sb + (uint32_t)(ks % 3) * 32768;
        uint32_t bbase = abase + 16384;
#pragma unroll
        for (int kc = 0; kc < 2; kc++) {
            uint32_t ah[2][4], al[2][4];
#pragma unroll
            for (int mf = 0; mf < 2; mf++) {
                int row = mw + mf * 16 + (lane & 15);
                int g = kc * 2 + (lane >> 4);
                uint32_t a = abase + swz(row, g);
                LDSM4(ah[mf][0], ah[mf][1], ah[mf][2], ah[mf][3], a);
                LDSM4(al[mf][0], al[mf][1], al[mf][2], al[mf][3], a + 8192);
            }
#pragma unroll
            for (int bp = 0; bp < 4; bp++) {
                int p = nw + bp * 16 + ((lane >> 4) << 3) + (lane & 7);
                int g = kc * 2 + ((lane >> 3) & 1);
                uint32_t a = bbase + swz(p, g);
                uint32_t h0, h1, h2, h3, l0, l1, l2, l3;
                LDSM4(h0, h1, h2, h3, a);
                LDSM4(l0, l1, l2, l3, a + 8192);
                MMA16816(acc[0][2 * bp],     ah[0][0], ah[0][1], ah[0][2], ah[0][3], h0, h1);
                MMA16816(acc[1][2 * bp],     ah[1][0], ah[1][1], ah[1][2], ah[1][3], h0, h1);
                MMA16816(acc[0][2 * bp + 1], ah[0][0], ah[0][1], ah[0][2], ah[0][3], h2, h3);
                MMA16816(acc[1][2 * bp + 1], ah[1][0], ah[1][1], ah[1][2], ah[1][3], h2, h3);
                MMA16816(acc[0][2 * bp],     ah[0][0], ah[0][1], ah[0][2], ah[0][3], l0, l1);
                MMA16816(acc[1][2 * bp],     ah[1][0], ah[1][1], ah[1][2], ah[1][3], l0, l1);
                MMA16816(acc[0][2 * bp + 1], ah[0][0], ah[0][1], ah[0][2], ah[0][3], l2, l3);
                MMA16816(acc[1][2 * bp + 1], ah[1][0], ah[1][1], ah[1][2], ah[1][3], l2, l3);
                MMA16816(acc[0][2 * bp],     al[0][0], al[0][1], al[0][2], al[0][3], h0, h1);
                MMA16816(acc[1][2 * bp],     al[1][0], al[1][1], al[1][2], al[1][3], h0, h1);
                MMA16816(acc[0][2 * bp + 1], al[0][0], al[0][1], al[0][2], al[0][3], h2, h3);
                MMA16816(acc[1][2 * bp + 1], al[1][0], al[1][1], al[1][2], al[1][3], h2, h3);
            }
        }
    }

#pragma unroll
    for (int mf = 0; mf < 2; mf++) {
        int r0 = m0 + mw + mf * 16 + (lane >> 2);
        int r1 = r0 + 8;
#pragma unroll
        for (int nf = 0; nf < 8; nf++) {
            float d0 = acc[mf][nf][0], d1 = acc[mf][nf][1];
            float d2 = acc[mf][nf][2], d3 = acc[mf][nf][3];
            int c0 = nw + nf * 8 + (lane & 3) * 2;
            if (mode == 2) {
                int gc = t * 128 + c0;
                float2 bb = *(const float2*)(aux + gc);
                float* dst = (gc < 128) ? (g_h + gc) : (g_c + gc - 128);
                if (r0 < n) {
                    float e0 = d0 + bb.x, e1 = d1 + bb.y;
                    e0 = (e0 > 0.f) ? e0 : expm1f(e0);
                    e1 = (e1 > 0.f) ? e1 : expm1f(e1);
                    float2 o; o.x = e0; o.y = e1;
                    *(float2*)(dst + (size_t)r0 * 128) = o;
                }
                if (r1 < n) {
                    float e0 = d2 + bb.x, e1 = d3 + bb.y;
                    e0 = (e0 > 0.f) ? e0 : expm1f(e0);
                    e1 = (e1 > 0.f) ? e1 : expm1f(e1);
                    float2 o; o.x = e0; o.y = e1;
                    *(float2*)(dst + (size_t)r1 * 128) = o;
                }
            } else {
                int P = t * 128 + c0;
                float bb0 = aux[(P & 3) * 128 + (P >> 2)];
                float bb1 = aux[((P + 1) & 3) * 128 + ((P + 1) >> 2)];
                if (r0 < n) {
                    float2 o; o.x = d0 + bb0; o.y = d1 + bb1;
                    *(float2*)(o512 + (size_t)r0 * 512 + P) = o;
                }
                if (r1 < n) {
                    float2 o; o.x = d2 + bb0; o.y = d3 + bb1;
                    *(float2*)(o512 + (size_t)r1 * 512 + P) = o;
                }
            }
        }
    }
}

// ---------------- host launcher ----------------
extern "C" void kernel_launch(void* const* d_in, const int* in_sizes, int n_in,
                              void* d_out, int out_size) {
    const float* h  = (const float*)d_in[0];
    const float* c  = (const float*)d_in[1];
    const void*  ei = d_in[2];
    const float* ea = (const float*)d_in[3];
    const float* Wi = (const float*)d_in[4];
    const float* bi = (const float*)d_in[5];
    const float* Wc = (const float*)d_in[6];
    const float* bc = (const float*)d_in[7];
    float* out = (float*)d_out;

    int n   = in_sizes[0] / 128;
    int E   = in_sizes[3];
    int seq = out_size / (n * 128);

    static float* p_base = nullptr;
    static float* p_h = nullptr;
    static __nv_bfloat16 *p_Ph, *p_Pl, *p_WTh, *p_WTl, *p_WIh, *p_WIl;
    if (!p_base) {
        cudaGetSymbolAddress((void**)&p_base, g_base);
        cudaGetSymbolAddress((void**)&p_h, g_h);
        cudaGetSymbolAddress((void**)&p_Ph, g_Ph);
        cudaGetSymbolAddress((void**)&p_Pl, g_Pl);
        cudaGetSymbolAddress((void**)&p_WTh, g_WTh);
        cudaGetSymbolAddress((void**)&p_WTl, g_WTl);
        cudaGetSymbolAddress((void**)&p_WIh, g_WIh);
        cudaGetSymbolAddress((void**)&p_WIl, g_WIl);
        cudaFuncSetAttribute(k_mma, cudaFuncAttributeMaxDynamicSharedMemorySize, 98304);
        cudaFuncSetAttribute(k_mmaS, cudaFuncAttributeMaxDynamicSharedMemorySize, 49152);
    }

    int nb256 = (n + 255) / 256;
    int eb256 = (E + 255) / 256;
    int nb1024 = (n + 1023) / 1024;
    int mtiles = (n + 127) / 128;
    int mt64 = (n + 63) / 64;
    int prop_blocks = (n * 32 + 255) / 256;
    size_t smem_sz = 98304;
    size_t smemS = 49152;

    // ---- graph setup (per launch; deterministic) ----
    k_init<<<nb256, 256>>>(n);
    k_detect<<<1, 128>>>((const unsigned int*)ei);
    k_build<<<eb256, 256>>>(ei, ea, E);
    k_scan1<<<nb1024, 1024>>>(n);        // also computes dinv
    k_scan2<<<1, 32>>>(nb1024);
    k_scan3<<<nb1024, 1024>>>(n);
    k_scatter<<<eb256, 256>>>(ea, E);
    k_split<<<1024, 256>>>(Wc, Wi);

    // ---- loop-invariant precompute ----
    k_prop<<<dim3(prop_blocks, 2), 256>>>(h, c, p_Ph, p_Pl, 256, n);
    // init: elu(Phc @ W_init + b_init) -> g_h, g_c
    k_mma<<<dim3(mtiles, 2), 256, smem_sz>>>(p_Ph, p_Pl, 256, p_WIh, p_WIl, 256,
                                             bi, nullptr, n, 2);
    // base_perm = P_h @ Wc[0:128] + b_cell
    k_mma<<<dim3(mtiles, 4), 256, smem_sz>>>(p_Ph, p_Pl, 256, p_WTh, p_WTl, 128,
                                             bc, p_base, n, 0);

    // ---- sequence: h(t) lives in out[t-1] slab ----
    const float* hsrc = p_h;
    for (int tt = 0; tt < seq; tt++) {
        k_prop16<<<prop_blocks, 256>>>(hsrc, n);
        float* odst = out + (long long)tt * n * 128;
        k_mmaS<<<dim3(mt64, 4), 256, smemS>>>(p_base, odst, n);
        hsrc = odst;
    }
}

// round 16
// speedup vs baseline: 1.5271x; 1.4301x over previous
#include <cuda_runtime.h>
#include <cuda_bf16.h>
#include <cuda_fp16.h>
#include <math.h>
#include <stdint.h>

#define MAXN 20000
#define MAXE 320000

// ---------------- device scratch (no allocs allowed) ----------------
__device__ int   g_is64;
__device__ int   g_src[MAXE];
__device__ int   g_dst[MAXE];
__device__ int   g_esrc[MAXE];
__device__ float g_ewn[MAXE];
__device__ float g_deg[MAXN];
__device__ float g_dinv[MAXN];
__device__ int   g_cnt[MAXN];
__device__ int   g_rowptr[MAXN + 1];
__device__ int   g_cursor[MAXN];
__device__ int   g_part[32];
__device__ int   g_off2[32];
__device__ int   g_total;
__device__ float g_base[(long long)MAXN * 512];   // permuted gate layout [r][P], P = hcol*4 + gate
__device__ float g_h[MAXN * 128];
__device__ float g_c[MAXN * 128];
// bf16-split activations (init path)
__device__ __nv_bfloat16 g_Ph[MAXN * 256];   // [P_h | P_c] hi
__device__ __nv_bfloat16 g_Pl[MAXN * 256];   // lo
// fp16-split activations (sequence path)
__device__ __half g_zh[MAXN * 128];
__device__ __half g_zl[MAXN * 128];
// bf16-split transposed weights (init/base), perm P = hcol*4 + gate
__device__ __nv_bfloat16 g_WTh[2 * 512 * 128];
__device__ __nv_bfloat16 g_WTl[2 * 512 * 128];
__device__ __nv_bfloat16 g_WIh[256 * 256];
__device__ __nv_bfloat16 g_WIl[256 * 256];
// fp16 single-precision weights for W_cell m=1 half (sequence path), permuted [P][k]
__device__ __half g_WF[512 * 128];

// ---------------- helpers ----------------
__device__ __forceinline__ float tanhA(float x) {
    float r; asm("tanh.approx.f32 %0, %1;" : "=f"(r) : "f"(x)); return r;
}
__device__ __forceinline__ float sigA(float x) {
    return fmaf(tanhA(0.5f * x), 0.5f, 0.5f);
}
__device__ __forceinline__ uint32_t smem_u32(const void* p) {
    uint32_t a;
    asm("{ .reg .u64 t; cvta.to.shared.u64 t, %1; cvt.u32.u64 %0, t; }" : "=r"(a) : "l"(p));
    return a;
}

#define CP16(dst, src, srcsz) \
    asm volatile("cp.async.ca.shared.global [%0], [%1], 16, %2;" \
        :: "r"(dst), "l"(src), "r"(srcsz))
#define CP_COMMIT() asm volatile("cp.async.commit_group;" ::: "memory")
#define CP_WAIT(nn) asm volatile("cp.async.wait_group %0;" :: "n"(nn) : "memory")

#define LDSM4(r0, r1, r2, r3, a) \
    asm volatile("ldmatrix.sync.aligned.m8n8.x4.shared.b16 {%0,%1,%2,%3}, [%4];" \
        : "=r"(r0), "=r"(r1), "=r"(r2), "=r"(r3) : "r"(a))

#define MMA16816(d, a0, a1, a2, a3, b0, b1) \
    asm volatile("mma.sync.aligned.m16n8k16.row.col.f32.bf16.bf16.f32 " \
        "{%0,%1,%2,%3}, {%4,%5,%6,%7}, {%8,%9}, {%0,%1,%2,%3};" \
        : "+f"((d)[0]), "+f"((d)[1]), "+f"((d)[2]), "+f"((d)[3]) \
        : "r"(a0), "r"(a1), "r"(a2), "r"(a3), "r"(b0), "r"(b1))

#define MMAH(d, a0, a1, a2, a3, b0, b1) \
    asm volatile("mma.sync.aligned.m16n8k16.row.col.f32.f16.f16.f32 " \
        "{%0,%1,%2,%3}, {%4,%5,%6,%7}, {%8,%9}, {%0,%1,%2,%3};" \
        : "+f"((d)[0]), "+f"((d)[1]), "+f"((d)[2]), "+f"((d)[3]) \
        : "r"(a0), "r"(a1), "r"(a2), "r"(a3), "r"(b0), "r"(b1))

// smem swizzle: 64B rows, 4x16B granules, conflict-free for 8-row LDSM phases
__device__ __forceinline__ uint32_t swz(int row, int g) {
    return (uint32_t)(row * 64 + ((g ^ ((row >> 1) & 3)) << 4));
}

// ---------------- setup kernels ----------------
__global__ void k_init(int n) {
    int i = blockIdx.x * blockDim.x + threadIdx.x;
    if (i < n) { g_deg[i] = 0.f; g_cnt[i] = 0; }
    if (i == 0) g_is64 = 1;
}

__global__ void k_detect(const unsigned int* __restrict__ w) {
    unsigned int v = w[2 * threadIdx.x + 1];
    if (v != 0u) g_is64 = 0;
}

__global__ void k_build(const void* __restrict__ ei, const float* __restrict__ ea, int E) {
    int e = blockIdx.x * blockDim.x + threadIdx.x;
    if (e >= E) return;
    int s, d;
    if (g_is64) {
        const long long* p = (const long long*)ei;
        s = (int)p[e]; d = (int)p[E + e];
    } else {
        const int* p = (const int*)ei;
        s = p[e]; d = p[E + e];
    }
    g_src[e] = s; g_dst[e] = d;
    atomicAdd(&g_deg[d], ea[e]);
    atomicAdd(&g_cnt[d], 1);
}

// hierarchical scan pass 1 (+ dinv fused)
__global__ void k_scan1(int n) {
    __shared__ int s[1024];
    int i = blockIdx.x * 1024 + threadIdx.x;
    if (i < n) g_dinv[i] = rsqrtf(g_deg[i] + 1.0f);
    int v = (i < n) ? g_cnt[i] : 0;
    s[threadIdx.x] = v;
    __syncthreads();
    for (int off = 1; off < 1024; off <<= 1) {
        int t = (threadIdx.x >= off) ? s[threadIdx.x - off] : 0;
        __syncthreads();
        s[threadIdx.x] += t;
        __syncthreads();
    }
    if (i < n) g_rowptr[i] = s[threadIdx.x] - v;   // local exclusive
    if (threadIdx.x == 1023) g_part[blockIdx.x] = s[1023];
}

__global__ void k_scan2(int nb) {
    int tid = threadIdx.x;                 // 32 threads
    int v = (tid < nb) ? g_part[tid] : 0;
    int incl = v;
    for (int o = 1; o < 32; o <<= 1) {
        int t = __shfl_up_sync(0xffffffffu, incl, o);
        if (tid >= o) incl += t;
    }
    if (tid < nb) g_off2[tid] = incl - v;
    if (tid == 31) g_total = incl;
}

__global__ void k_scan3(int n) {
    int i = blockIdx.x * 1024 + threadIdx.x;
    if (i < n) {
        int val = g_rowptr[i] + g_off2[blockIdx.x];
        g_rowptr[i] = val;
        g_cursor[i] = val;
    }
    if (i == 0) g_rowptr[n] = g_total;
}

__global__ void k_scatter(const float* __restrict__ ea, int E) {
    int e = blockIdx.x * blockDim.x + threadIdx.x;
    if (e >= E) return;
    int s = g_src[e], d = g_dst[e];
    int pos = atomicAdd(&g_cursor[d], 1);
    g_esrc[pos] = s;
    g_ewn[pos] = g_dinv[s] * ea[e] * g_dinv[d];
}

// fused weight transpose + permute + splits
// ids [0, 131072): W_cell bf16 split; perm P = hcol*4 + q <-> orig col q*128 + hcol
// ids [131072, 196608): W_init bf16 split, transposed [p][k]
// ids [196608, 262144): g_WF fp16 single of W_cell m=1 half, permuted [P][k]
__global__ void k_split(const float* __restrict__ Wc, const float* __restrict__ Wi) {
    int id = blockIdx.x * blockDim.x + threadIdx.x;   // 0 .. 262143
    if (id < 131072) {
        int m = id >> 16;
        int rem = id & 65535;
        int p = rem >> 7;
        int k = rem & 127;
        int hcol = p >> 2, q = p & 3;
        int nc = q * 128 + hcol;
        float v = Wc[(long long)(m * 128 + k) * 512 + nc];
        __nv_bfloat16 hb = __float2bfloat16_rn(v);
        float lf = v - __bfloat162float(hb);
        g_WTh[id] = hb;
        g_WTl[id] = __float2bfloat16_rn(lf);
    } else if (id < 196608) {
        int id2 = id - 131072;
        int p = id2 >> 8;
        int k = id2 & 255;
        float v = Wi[(long long)k * 256 + p];
        __nv_bfloat16 hb = __float2bfloat16_rn(v);
        float lf = v - __bfloat162float(hb);
        g_WIh[id2] = hb;
        g_WIl[id2] = __float2bfloat16_rn(lf);
    } else {
        int id3 = id - 196608;
        int P = id3 >> 7;
        int k = id3 & 127;
        int hcol = P >> 2, q = P & 3;
        float v = Wc[(long long)(128 + k) * 512 + q * 128 + hcol];
        g_WF[id3] = __float2half_rn(v);
    }
}

// ---------------- sparse propagate -> bf16 hi/lo split output (init path) ------
__global__ void k_prop(const float* __restrict__ x0, const float* __restrict__ x1,
                       __nv_bfloat16* __restrict__ oh, __nv_bfloat16* __restrict__ ol,
                       int ldo, int n) {
    const float* x = blockIdx.y ? x1 : x0;
    int coff = blockIdx.y * 128;
    int v = (blockIdx.x * blockDim.x + threadIdx.x) >> 5;
    int lane = threadIdx.x & 31;
    if (v >= n) return;
    int beg = g_rowptr[v], end = g_rowptr[v + 1];
    float ax = 0.f, ay = 0.f, az = 0.f, aw = 0.f;
    int e = beg;
    for (; e + 1 < end; e += 2) {
        int s0 = g_esrc[e], s1 = g_esrc[e + 1];
        float w0 = g_ewn[e], w1 = g_ewn[e + 1];
        float4 v0 = __ldg((const float4*)(x + (long long)s0 * 128) + lane);
        float4 v1 = __ldg((const float4*)(x + (long long)s1 * 128) + lane);
        ax = fmaf(w0, v0.x, ax); ay = fmaf(w0, v0.y, ay);
        az = fmaf(w0, v0.z, az); aw = fmaf(w0, v0.w, aw);
        ax = fmaf(w1, v1.x, ax); ay = fmaf(w1, v1.y, ay);
        az = fmaf(w1, v1.z, az); aw = fmaf(w1, v1.w, aw);
    }
    if (e < end) {
        int s0 = g_esrc[e];
        float w0 = g_ewn[e];
        float4 v0 = __ldg((const float4*)(x + (long long)s0 * 128) + lane);
        ax = fmaf(w0, v0.x, ax); ay = fmaf(w0, v0.y, ay);
        az = fmaf(w0, v0.z, az); aw = fmaf(w0, v0.w, aw);
    }
    float di = g_dinv[v];
    float w2 = di * di;
    float4 vv = __ldg((const float4*)(x + (long long)v * 128) + lane);
    ax = fmaf(w2, vv.x, ax); ay = fmaf(w2, vv.y, ay);
    az = fmaf(w2, vv.z, az); aw = fmaf(w2, vv.w, aw);
    float a[4] = {ax, ay, az, aw};
    unsigned short hs[4], ls[4];
#pragma unroll
    for (int m = 0; m < 4; m++) {
        __nv_bfloat16 hb = __float2bfloat16_rn(a[m]);
        float lf = a[m] - __bfloat162float(hb);
        __nv_bfloat16 lb = __float2bfloat16_rn(lf);
        hs[m] = *(unsigned short*)&hb;
        ls[m] = *(unsigned short*)&lb;
    }
    *(uint2*)(oh + (long long)v * ldo + coff + lane * 4) = *(uint2*)hs;
    *(uint2*)(ol + (long long)v * ldo + coff + lane * 4) = *(uint2*)ls;
}

// ---------------- sparse propagate -> fp16 hi/lo split output (sequence path) ----
__global__ void k_prop16(const float* __restrict__ x, int n) {
    int v = (blockIdx.x * blockDim.x + threadIdx.x) >> 5;
    int lane = threadIdx.x & 31;
    if (v >= n) return;
    int beg = g_rowptr[v], end = g_rowptr[v + 1];
    float ax = 0.f, ay = 0.f, az = 0.f, aw = 0.f;
    int e = beg;
    for (; e + 1 < end; e += 2) {
        int s0 = g_esrc[e], s1 = g_esrc[e + 1];
        float w0 = g_ewn[e], w1 = g_ewn[e + 1];
        float4 v0 = __ldg((const float4*)(x + (long long)s0 * 128) + lane);
        float4 v1 = __ldg((const float4*)(x + (long long)s1 * 128) + lane);
        ax = fmaf(w0, v0.x, ax); ay = fmaf(w0, v0.y, ay);
        az = fmaf(w0, v0.z, az); aw = fmaf(w0, v0.w, aw);
        ax = fmaf(w1, v1.x, ax); ay = fmaf(w1, v1.y, ay);
        az = fmaf(w1, v1.z, az); aw = fmaf(w1, v1.w, aw);
    }
    if (e < end) {
        int s0 = g_esrc[e];
        float w0 = g_ewn[e];
        float4 v0 = __ldg((const float4*)(x + (long long)s0 * 128) + lane);
        ax = fmaf(w0, v0.x, ax); ay = fmaf(w0, v0.y, ay);
        az = fmaf(w0, v0.z, az); aw = fmaf(w0, v0.w, aw);
    }
    float di = g_dinv[v];
    float w2 = di * di;
    float4 vv = __ldg((const float4*)(x + (long long)v * 128) + lane);
    ax = fmaf(w2, vv.x, ax); ay = fmaf(w2, vv.y, ay);
    az = fmaf(w2, vv.z, az); aw = fmaf(w2, vv.w, aw);
    float a[4] = {ax, ay, az, aw};
    unsigned short hs[4], ls[4];
#pragma unroll
    for (int m = 0; m < 4; m++) {
        __half hb = __float2half_rn(a[m]);
        float lf = a[m] - __half2float(hb);
        __half lb = __float2half_rn(lf);
        hs[m] = *(unsigned short*)&hb;
        ls[m] = *(unsigned short*)&lb;
    }
    *(uint2*)(g_zh + (long long)v * 128 + lane * 4) = *(uint2*)hs;
    *(uint2*)(g_zl + (long long)v * 128 + lane * 4) = *(uint2*)ls;
}

// ---------------- sequence GEMM: fp16 2-term, M64 x N128 tile ----------------
// D = (Xh + Xl) @ W^T ; X fp16 hi/lo (22-bit activation), W single fp16.
// smem per 16KB stage: Ah[0,4K) Al[4K,8K) W[8K,16K); 64B swizzled rows; 2 stages.
// gates = D + base_perm; LSTM update g_c; write oseq.
__global__ void __launch_bounds__(256, 3)
k_mmaS(const float* __restrict__ baseb, float* __restrict__ oseq, int n) {
    extern __shared__ char sm[];
    const uint32_t sb = smem_u32(sm);
    const int tid = threadIdx.x;
    const int lane = tid & 31;
    const int wid = tid >> 5;
    const int m0 = blockIdx.x * 64;
    const int t = blockIdx.y;
    const int mw = (wid & 1) * 32;
    const int nw = (wid >> 1) * 32;

    float acc[2][4][4];
#pragma unroll
    for (int i = 0; i < 2; i++)
#pragma unroll
        for (int j = 0; j < 4; j++)
#pragma unroll
            for (int q = 0; q < 4; q++) acc[i][j][q] = 0.f;

    auto stage = [&](int ks) {
        uint32_t bufo = (uint32_t)(ks & 1) * 16384;
#pragma unroll
        for (int it = 0; it < 4; it++) {
            int id = tid + it * 256;        // 0..1023
            if (id < 512) {
                int arr = id >> 8;          // 0:zh 1:zl
                int rem = id & 255;
                int row = rem >> 2, g = rem & 3;
                uint32_t dst = sb + bufo + arr * 4096 + swz(row, g);
                const __half* src = (arr == 0 ? g_zh : g_zl)
                    + (size_t)(m0 + row) * 128 + ks * 32 + g * 8;
                int ok = (m0 + row < n) ? 16 : 0;
                CP16(dst, src, ok);
            } else {
                int rem = id - 512;         // 0..511
                int row = rem >> 2, g = rem & 3;
                uint32_t dst = sb + bufo + 8192 + swz(row, g);
                const __half* src = g_WF
                    + (size_t)(t * 128 + row) * 128 + ks * 32 + g * 8;
                CP16(dst, src, 16);
            }
        }
        CP_COMMIT();
    };

    stage(0);
#pragma unroll
    for (int ks = 0; ks < 4; ks++) {
        if (ks + 1 < 4) { stage(ks + 1); CP_WAIT(1); } else { CP_WAIT(0); }
        __syncthreads();
        uint32_t abase = sb + (uint32_t)(ks & 1) * 16384;
        uint32_t bbase = abase + 8192;
#pragma unroll
        for (int kc = 0; kc < 2; kc++) {
            uint32_t ah[2][4], al[2][4];
#pragma unroll
            for (int mf = 0; mf < 2; mf++) {
                int row = mw + mf * 16 + (lane & 15);
                int g = kc * 2 + (lane >> 4);
                uint32_t a = abase + swz(row, g);
                LDSM4(ah[mf][0], ah[mf][1], ah[mf][2], ah[mf][3], a);
                LDSM4(al[mf][0], al[mf][1], al[mf][2], al[mf][3], a + 4096);
            }
            uint32_t wf[2][4];
#pragma unroll
            for (int bp = 0; bp < 2; bp++) {
                int p = nw + bp * 16 + ((lane >> 4) << 3) + (lane & 7);
                int g = kc * 2 + ((lane >> 3) & 1);
                uint32_t a = bbase + swz(p, g);
                LDSM4(wf[bp][0], wf[bp][1], wf[bp][2], wf[bp][3], a);
            }
            // 16 MMAs: Xh term then Xl term (reuse distance 8)
#pragma unroll
            for (int bp = 0; bp < 2; bp++) {
                MMAH(acc[0][2 * bp],     ah[0][0], ah[0][1], ah[0][2], ah[0][3], wf[bp][0], wf[bp][1]);
                MMAH(acc[1][2 * bp],     ah[1][0], ah[1][1], ah[1][2], ah[1][3], wf[bp][0], wf[bp][1]);
                MMAH(acc[0][2 * bp + 1], ah[0][0], ah[0][1], ah[0][2], ah[0][3], wf[bp][2], wf[bp][3]);
                MMAH(acc[1][2 * bp + 1], ah[1][0], ah[1][1], ah[1][2], ah[1][3], wf[bp][2], wf[bp][3]);
            }
#pragma unroll
            for (int bp = 0; bp < 2; bp++) {
                MMAH(acc[0][2 * bp],     al[0][0], al[0][1], al[0][2], al[0][3], wf[bp][0], wf[bp][1]);
                MMAH(acc[1][2 * bp],     al[1][0], al[1][1], al[1][2], al[1][3], wf[bp][0], wf[bp][1]);
                MMAH(acc[0][2 * bp + 1], al[0][0], al[0][1], al[0][2], al[0][3], wf[bp][2], wf[bp][3]);
                MMAH(acc[1][2 * bp + 1], al[1][0], al[1][1], al[1][2], al[1][3], wf[bp][2], wf[bp][3]);
            }
        }
        __syncthreads();
    }

    // ---- LSTM epilogue ----
#pragma unroll
    for (int mf = 0; mf < 2; mf++) {
        int r0 = m0 + mw + mf * 16 + (lane >> 2);
        int r1 = r0 + 8;
#pragma unroll
        for (int nf = 0; nf < 4; nf++) {
            float d0 = acc[mf][nf][0], d1 = acc[mf][nf][1];
            float d2 = acc[mf][nf][2], d3 = acc[mf][nf][3];
            int c0 = nw + nf * 8 + (lane & 3) * 2;
            int P0 = t * 128 + c0;
            float2 b0 = make_float2(0.f, 0.f), b1 = make_float2(0.f, 0.f);
            if (r0 < n) b0 = *(const float2*)(baseb + (size_t)r0 * 512 + P0);
            if (r1 < n) b1 = *(const float2*)(baseb + (size_t)r1 * 512 + P0);
            float v0 = d0 + b0.x, v1 = d1 + b0.y;
            float v2 = d2 + b1.x, v3 = d3 + b1.y;
            float u0 = __shfl_xor_sync(0xffffffffu, v0, 1);
            float u1 = __shfl_xor_sync(0xffffffffu, v1, 1);
            float u2 = __shfl_xor_sync(0xffffffffu, v2, 1);
            float u3 = __shfl_xor_sync(0xffffffffu, v3, 1);
            if (!(lane & 1)) {
                // this lane: (i, f); partner: (o, g)
                int hcol = P0 >> 2;
                if (r0 < n) {
                    size_t ix = (size_t)r0 * 128 + hcol;
                    float cold = g_c[ix];
                    float cn = sigA(v1) * cold + sigA(v0) * tanhA(u1);
                    float hn = sigA(u0) * tanhA(cn);
                    g_c[ix] = cn; oseq[ix] = hn;
                }
                if (r1 < n) {
                    size_t ix = (size_t)r1 * 128 + hcol;
                    float cold = g_c[ix];
                    float cn = sigA(v3) * cold + sigA(v2) * tanhA(u3);
                    float hn = sigA(u2) * tanhA(cn);
                    g_c[ix] = cn; oseq[ix] = hn;
                }
            }
        }
    }
}

// ---------------- bf16 split-3 tensor GEMM (init + base precompute) ----------------
// mode 0: o512[r*512 + P] = D + bc[orig col]   (permuted base precompute)
// mode 2: init: elu(D + bi[col]) -> g_h (cols<128) / g_c
__global__ void __launch_bounds__(256, 2)
k_mma(const __nv_bfloat16* __restrict__ Ah, const __nv_bfloat16* __restrict__ Al, int lda,
      const __nv_bfloat16* __restrict__ Bh, const __nv_bfloat16* __restrict__ Bl,
      int K, const float* __restrict__ aux, float* __restrict__ o512, int n, int mode) {
    extern __shared__ char sm[];
    const uint32_t sb = smem_u32(sm);
    const int tid = threadIdx.x;
    const int lane = tid & 31;
    const int wid = tid >> 5;
    const int m0 = blockIdx.x * 128;
    const int t = blockIdx.y;
    const int mw = (wid & 3) * 32;
    const int nw = (wid >> 2) * 64;

    float acc[2][8][4];
#pragma unroll
    for (int i = 0; i < 2; i++)
#pragma unroll
        for (int j = 0; j < 8; j++)
#pragma unroll
            for (int q = 0; q < 4; q++) acc[i][j][q] = 0.f;

    const int nslab = K >> 5;

    auto stage = [&](int ks) {
        uint32_t bufo = (uint32_t)(ks % 3) * 32768;
#pragma unroll
        for (int it = 0; it < 8; it++) {
            int id = tid + it * 256;
            int arr = id >> 9;
            int rem = id & 511;
            int row = rem >> 2, g = rem & 3;
            uint32_t dst = sb + bufo + arr * 8192 + swz(row, g);
            if (arr < 2) {
                const __nv_bfloat16* src = (arr == 0 ? Ah : Al)
                    + (size_t)(m0 + row) * lda + ks * 32 + g * 8;
                int ok = (m0 + row < n) ? 16 : 0;
                CP16(dst, src, ok);
            } else {
                const __nv_bfloat16* src = (arr == 2 ? Bh : Bl)
                    + (size_t)(t * 128 + row) * K + ks * 32 + g * 8;
                CP16(dst, src, 16);
            }
        }
        CP_COMMIT();
    };

    stage(0);
    stage(1);
    for (int ks = 0; ks < nslab; ks++) {
        if (ks == nslab - 1) { CP_WAIT(0); } else { CP_WAIT(1); }
        __syncthreads();
        if (ks + 2 < nslab) stage(ks + 2);
        uint32_t abase = sb + (uint32_t)(ks % 3) * 32768;
        uint32_t bbase = abase + 16384;
#pragma unroll
        for (int kc = 0; kc < 2; kc++) {
            uint32_t ah[2][4], al[2][4];
#pragma unroll
            for (int mf = 0; mf < 2; mf++) {
                int row = mw + mf * 16 + (lane & 15);
                int g = kc * 2 + (lane >> 4);
                uint32_t a = abase + swz(row, g);
                LDSM4(ah[mf][0], ah[mf][1], ah[mf][2], ah[mf][3], a);
                LDSM4(al[mf][0], al[mf][1], al[mf][2], al[mf][3], a + 8192);
            }
#pragma unroll
            for (int bp = 0; bp < 4; bp++) {
                int p = nw + bp * 16 + ((lane >> 4) << 3) + (lane & 7);
                int g = kc * 2 + ((lane >> 3) & 1);
                uint32_t a = bbase + swz(p, g);
                uint32_t h0, h1, h2, h3, l0, l1, l2, l3;
                LDSM4(h0, h1, h2, h3, a);
                LDSM4(l0, l1, l2, l3, a + 8192);
                MMA16816(acc[0][2 * bp],     ah[0][0], ah[0][1], ah[0][2], ah[0][3], h0, h1);
                MMA16816(acc[1][2 * bp],     ah[1][0], ah[1][1], ah[1][2], ah[1][3], h0, h1);
                MMA16816(acc[0][2 * bp + 1], ah[0][0], ah[0][1], ah[0][2], ah[0][3], h2, h3);
                MMA16816(acc[1][2 * bp + 1], ah[1][0], ah[1][1], ah[1][2], ah[1][3], h2, h3);
                MMA16816(acc[0][2 * bp],     ah[0][0], ah[0][1], ah[0][2], ah[0][3], l0, l1);
                MMA16816(acc[1][2 * bp],     ah[1][0], ah[1][1], ah[1][2], ah[1][3], l0, l1);
                MMA16816(acc[0][2 * bp + 1], ah[0][0], ah[0][1], ah[0][2], ah[0][3], l2, l3);
                MMA16816(acc[1][2 * bp + 1], ah[1][0], ah[1][1], ah[1][2], ah[1][3], l2, l3);
                MMA16816(acc[0][2 * bp],     al[0][0], al[0][1], al[0][2], al[0][3], h0, h1);
                MMA16816(acc[1][2 * bp],     al[1][0], al[1][1], al[1][2], al[1][3], h0, h1);
                MMA16816(acc[0][2 * bp + 1], al[0][0], al[0][1], al[0][2], al[0][3], h2, h3);
                MMA16816(acc[1][2 * bp + 1], al[1][0], al[1][1], al[1][2], al[1][3], h2, h3);
            }
        }
    }

#pragma unroll
    for (int mf = 0; mf < 2; mf++) {
        int r0 = m0 + mw + mf * 16 + (lane >> 2);
        int r1 = r0 + 8;
#pragma unroll
        for (int nf = 0; nf < 8; nf++) {
            float d0 = acc[mf][nf][0], d1 = acc[mf][nf][1];
            float d2 = acc[mf][nf][2], d3 = acc[mf][nf][3];
            int c0 = nw + nf * 8 + (lane & 3) * 2;
            if (mode == 2) {
                int gc = t * 128 + c0;
                float2 bb = *(const float2*)(aux + gc);
                float* dst = (gc < 128) ? (g_h + gc) : (g_c + gc - 128);
                if (r0 < n) {
                    float e0 = d0 + bb.x, e1 = d1 + bb.y;
                    e0 = (e0 > 0.f) ? e0 : expm1f(e0);
                    e1 = (e1 > 0.f) ? e1 : expm1f(e1);
                    float2 o; o.x = e0; o.y = e1;
                    *(float2*)(dst + (size_t)r0 * 128) = o;
                }
                if (r1 < n) {
                    float e0 = d2 + bb.x, e1 = d3 + bb.y;
                    e0 = (e0 > 0.f) ? e0 : expm1f(e0);
                    e1 = (e1 > 0.f) ? e1 : expm1f(e1);
                    float2 o; o.x = e0; o.y = e1;
                    *(float2*)(dst + (size_t)r1 * 128) = o;
                }
            } else {
                int P = t * 128 + c0;
                float bb0 = aux[(P & 3) * 128 + (P >> 2)];
                float bb1 = aux[((P + 1) & 3) * 128 + ((P + 1) >> 2)];
                if (r0 < n) {
                    float2 o; o.x = d0 + bb0; o.y = d1 + bb1;
                    *(float2*)(o512 + (size_t)r0 * 512 + P) = o;
                }
                if (r1 < n) {
                    float2 o; o.x = d2 + bb0; o.y = d3 + bb1;
                    *(float2*)(o512 + (size_t)r1 * 512 + P) = o;
                }
            }
        }
    }
}

// ---------------- host launcher ----------------
extern "C" void kernel_launch(void* const* d_in, const int* in_sizes, int n_in,
                              void* d_out, int out_size) {
    const float* h  = (const float*)d_in[0];
    const float* c  = (const float*)d_in[1];
    const void*  ei = d_in[2];
    const float* ea = (const float*)d_in[3];
    const float* Wi = (const float*)d_in[4];
    const float* bi = (const float*)d_in[5];
    const float* Wc = (const float*)d_in[6];
    const float* bc = (const float*)d_in[7];
    float* out = (float*)d_out;

    int n   = in_sizes[0] / 128;
    int E   = in_sizes[3];
    int seq = out_size / (n * 128);

    static float* p_base = nullptr;
    static float* p_h = nullptr;
    static __nv_bfloat16 *p_Ph, *p_Pl, *p_WTh, *p_WTl, *p_WIh, *p_WIl;
    if (!p_base) {
        cudaGetSymbolAddress((void**)&p_base, g_base);
        cudaGetSymbolAddress((void**)&p_h, g_h);
        cudaGetSymbolAddress((void**)&p_Ph, g_Ph);
        cudaGetSymbolAddress((void**)&p_Pl, g_Pl);
        cudaGetSymbolAddress((void**)&p_WTh, g_WTh);
        cudaGetSymbolAddress((void**)&p_WTl, g_WTl);
        cudaGetSymbolAddress((void**)&p_WIh, g_WIh);
        cudaGetSymbolAddress((void**)&p_WIl, g_WIl);
        cudaFuncSetAttribute(k_mma, cudaFuncAttributeMaxDynamicSharedMemorySize, 98304);
        cudaFuncSetAttribute(k_mmaS, cudaFuncAttributeMaxDynamicSharedMemorySize, 32768);
    }

    int nb256 = (n + 255) / 256;
    int eb256 = (E + 255) / 256;
    int nb1024 = (n + 1023) / 1024;
    int mtiles = (n + 127) / 128;
    int mt64 = (n + 63) / 64;
    int prop_blocks = (n * 32 + 255) / 256;
    size_t smem_sz = 98304;
    size_t smemS = 32768;

    // ---- graph setup (per launch; deterministic) ----
    k_init<<<nb256, 256>>>(n);
    k_detect<<<1, 128>>>((const unsigned int*)ei);
    k_build<<<eb256, 256>>>(ei, ea, E);
    k_scan1<<<nb1024, 1024>>>(n);        // also computes dinv
    k_scan2<<<1, 32>>>(nb1024);
    k_scan3<<<nb1024, 1024>>>(n);
    k_scatter<<<eb256, 256>>>(ea, E);
    k_split<<<1024, 256>>>(Wc, Wi);

    // ---- loop-invariant precompute ----
    k_prop<<<dim3(prop_blocks, 2), 256>>>(h, c, p_Ph, p_Pl, 256, n);
    // init: elu(Phc @ W_init + b_init) -> g_h, g_c
    k_mma<<<dim3(mtiles, 2), 256, smem_sz>>>(p_Ph, p_Pl, 256, p_WIh, p_WIl, 256,
                                             bi, nullptr, n, 2);
    // base_perm = P_h @ Wc[0:128] + b_cell
    k_mma<<<dim3(mtiles, 4), 256, smem_sz>>>(p_Ph, p_Pl, 256, p_WTh, p_WTl, 128,
                                             bc, p_base, n, 0);

    // ---- sequence: h(t) lives in out[t-1] slab ----
    const float* hsrc = p_h;
    for (int tt = 0; tt < seq; tt++) {
        k_prop16<<<prop_blocks, 256>>>(hsrc, n);
        float* odst = out + (long long)tt * n * 128;
        k_mmaS<<<dim3(mt64, 4), 256, smemS>>>(p_base, odst, n);
        hsrc = odst;
    }
}